// round 1
// baseline (speedup 1.0000x reference)
#include <cuda_runtime.h>
#include <cuda_bf16.h>
#include <cstdint>

// ---------------------------------------------------------------------------
// DifferentialDropout: x [64, D], noise [64, D]  (D = 512*28*28 = 401408)
//   1. gram_stats: one pass over x -> Gram G (64x64, bf16 tensor cores),
//      row sums S, per-row 1024-bin presence bitmasks (rounded-value sets)
//   2. finalize: factors -> p  (fp64, 1 block); writes p to out[N..out_size)
//   3. dropout: out = noise >= p ? x/(1-p) : 0   (float4, memory-bound)
// ---------------------------------------------------------------------------

static __device__ float        g_S[64];
static __device__ float        g_G[64 * 64];
static __device__ unsigned int g_maskw[64 * 32];   // 1024 bins per row
static __device__ float        g_p;

// ---------------------------- zero scratch ---------------------------------
__global__ void zero_kernel() {
    int tid = blockIdx.x * blockDim.x + threadIdx.x;
    int stride = gridDim.x * blockDim.x;
    for (int i = tid; i < 64; i += stride)        g_S[i] = 0.f;
    for (int i = tid; i < 64 * 64; i += stride)   g_G[i] = 0.f;
    for (int i = tid; i < 64 * 32; i += stride)   g_maskw[i] = 0u;
}

// Swizzled bf16 tile: sh viewed as u32[64][32]; 16B chunk c of row r lives at
// physical chunk c ^ (r&7)  -> ldmatrix reads are bank-conflict free.
__device__ __forceinline__ int swz(int r, int w) {
    return (r << 5) + ((((w >> 2) ^ (r & 7)) << 2) | (w & 3));
}

// ------------------- fused stats + bf16 Gram (reads x once) ----------------
__global__ __launch_bounds__(256, 4)
void gram_stats_kernel(const float* __restrict__ x, int D, int ntiles) {
    __shared__ uint32_t sh[64 * 32];   // 64 rows x 64 bf16 (swizzled)

    const int tid  = threadIdx.x;
    const int lane = tid & 31;
    const int warp = tid >> 5;

    // loader mapping: 4 threads per row, 16 float4 per row-tile
    const int lrow = tid >> 2;     // 0..63
    const int lc   = tid & 3;      // 0..3

    // compute mapping: warp = (mb, nh); covers 16 rows x 32 cols of G
    const int mb = warp & 3;       // i0 = mb*16
    const int nh = warp >> 2;      // j base = nh*32
    const int i0 = mb << 4;

    // ldmatrix lane roles
    const int am  = lane & 7;          // row-within-8
    const int atr = (lane >> 3) & 1;   // +8 rows (A tiles 1,3)
    const int atc = lane >> 4;         // +1 chunk (A tiles 2,3)
    const int bm  = lane & 7;
    const int btl = (lane >> 3) & 1;   // +1 chunk (B tile 1)

    float acc[4][4];
    #pragma unroll
    for (int t = 0; t < 4; ++t)
        #pragma unroll
        for (int r = 0; r < 4; ++r) acc[t][r] = 0.f;

    float rsum = 0.f;
    unsigned long long rmask = 0ull;

    const uint32_t sbase = (uint32_t)__cvta_generic_to_shared(sh);

    for (int t = blockIdx.x; t < ntiles; t += gridDim.x) {
        __syncthreads();   // protect sh against previous iteration's readers
        const int k0 = t << 6;
        const float* rp = x + (size_t)lrow * D + k0;

        #pragma unroll
        for (int i = 0; i < 4; ++i) {
            const int j4 = (i << 2) + lc;                       // float4 idx 0..15
            float4 v = *reinterpret_cast<const float4*>(rp + (j4 << 2));
            rsum += (v.x + v.y) + (v.z + v.w);

            float vals[4] = {v.x, v.y, v.z, v.w};
            #pragma unroll
            for (int e = 0; e < 4; ++e) {
                int b = __float2int_rn(vals[e]);                // == jnp.round
                if ((unsigned)(b + 32) < 64u) {
                    rmask |= 1ull << (b + 32);
                } else {                                        // never for N(0,1)
                    int wb = b + 512;
                    wb = wb < 0 ? 0 : (wb > 1023 ? 1023 : wb);
                    atomicOr(&g_maskw[(lrow << 5) + (wb >> 5)], 1u << (wb & 31));
                }
            }

            __nv_bfloat162 p0 = __floats2bfloat162_rn(v.x, v.y);
            __nv_bfloat162 p1 = __floats2bfloat162_rn(v.z, v.w);
            const int wi = swz(lrow, j4 << 1);
            sh[wi]     = *reinterpret_cast<uint32_t*>(&p0);
            sh[wi + 1] = *reinterpret_cast<uint32_t*>(&p1);
        }
        __syncthreads();

        // G-tile update: 4 k-steps of 16, warp does 4 (m16n8) tiles per k-step
        #pragma unroll
        for (int ks = 0; ks < 4; ++ks) {
            const int cb = ks << 1;    // 16B-chunk base within row
            uint32_t a0, a1, a2, a3;
            {
                int r = i0 + (atr << 3) + am;   // (r & 7) == am
                uint32_t addr = sbase + (uint32_t)((r << 7) + (((cb + atc) ^ am) << 4));
                asm volatile("ldmatrix.sync.aligned.m8n8.x4.shared.b16 {%0,%1,%2,%3}, [%4];"
                             : "=r"(a0), "=r"(a1), "=r"(a2), "=r"(a3) : "r"(addr));
            }
            #pragma unroll
            for (int nt = 0; nt < 4; ++nt) {
                const int j0 = (nh << 5) + (nt << 3);
                uint32_t b0, b1;
                {
                    int r = j0 + bm;            // (r & 7) == bm
                    uint32_t addr = sbase + (uint32_t)((r << 7) + (((cb + btl) ^ bm) << 4));
                    asm volatile("ldmatrix.sync.aligned.m8n8.x2.shared.b16 {%0,%1}, [%2];"
                                 : "=r"(b0), "=r"(b1) : "r"(addr));
                }
                asm volatile("mma.sync.aligned.m16n8k16.row.col.f32.bf16.bf16.f32 "
                             "{%0,%1,%2,%3}, {%4,%5,%6,%7}, {%8,%9}, {%0,%1,%2,%3};"
                             : "+f"(acc[nt][0]), "+f"(acc[nt][1]),
                               "+f"(acc[nt][2]), "+f"(acc[nt][3])
                             : "r"(a0), "r"(a1), "r"(a2), "r"(a3), "r"(b0), "r"(b1));
            }
        }
    }

    // ---- per-row stats reduce (4 adjacent lanes per row) ----
    rsum += __shfl_xor_sync(0xffffffffu, rsum, 1);
    rsum += __shfl_xor_sync(0xffffffffu, rsum, 2);
    rmask |= __shfl_xor_sync(0xffffffffu, rmask, 1);
    rmask |= __shfl_xor_sync(0xffffffffu, rmask, 2);
    if (lc == 0) {
        atomicAdd(&g_S[lrow], rsum);
        // local bit (b+32) maps to wide bins 480..543 = words 15,16
        atomicOr(&g_maskw[(lrow << 5) + 15], (uint32_t)(rmask & 0xffffffffull));
        atomicOr(&g_maskw[(lrow << 5) + 16], (uint32_t)(rmask >> 32));
    }

    // ---- Gram partials -> global ----
    const int oi = i0 + (lane >> 2);
    #pragma unroll
    for (int nt = 0; nt < 4; ++nt) {
        const int oj = (nh << 5) + (nt << 3) + ((lane & 3) << 1);
        atomicAdd(&g_G[oi * 64 + oj],           acc[nt][0]);
        atomicAdd(&g_G[oi * 64 + oj + 1],       acc[nt][1]);
        atomicAdd(&g_G[(oi + 8) * 64 + oj],     acc[nt][2]);
        atomicAdd(&g_G[(oi + 8) * 64 + oj + 1], acc[nt][3]);
    }
}

// ----------------------------- finalize ------------------------------------
__global__ void finalize_kernel(const float* __restrict__ x,
                                const float* __restrict__ noise,
                                float* __restrict__ out,
                                long long N, long long out_size, int D) {
    __shared__ double sh_S[64], sh_std[64], sh_R[64], sh_mse[64];
    __shared__ int    sh_pu[64], sh_orw[32];
    __shared__ float  sh_cand[64];

    const int i = threadIdx.x;
    const double Dd = (double)D;

    if (i < 64) {
        double Si = (double)g_S[i];
        sh_S[i] = Si;
        double R = 0.0;
        for (int j = 0; j < 64; ++j) R += (double)g_G[i * 64 + j];
        sh_R[i] = R;
        double covii = ((double)g_G[i * 64 + i] - Si * Si / Dd) / (Dd - 1.0);
        sh_std[i] = sqrt(covii);
        int pu = 0;
        for (int w = 0; w < 32; ++w) pu += __popc(g_maskw[i * 32 + w]);
        sh_pu[i] = pu;
    }
    if (i < 32) {
        unsigned o = 0;
        for (int r = 0; r < 64; ++r) o |= g_maskw[r * 32 + i];
        sh_orw[i] = __popc(o);
    }
    __syncthreads();

    if (i < 64) {
        double T = 0.0;
        for (int j = 0; j < 64; ++j) T += sh_R[j];
        double Gii = (double)g_G[i * 64 + i];
        sh_mse[i] = (Gii - 2.0 * sh_R[i] / 64.0 + T / 4096.0) / Dd;
    }
    __syncthreads();

    if (i < 64) {
        double tot = 0.0;
        for (int j = 0; j < 64; ++j) tot += sh_mse[j];
        int tu = 0;
        for (int w = 0; w < 32; ++w) tu += sh_orw[w];

        const double Si = sh_S[i], si = sh_std[i];
        double f1 = 0.0;
        for (int j = 0; j < 64; ++j) {
            double cov = ((double)g_G[i * 64 + j] - Si * sh_S[j] / Dd) / (Dd - 1.0);
            double c = cov / (si * sh_std[j]);
            c = fmin(fmax(c, -1.0), 1.0);
            f1 += fabs(c);
        }
        f1 /= 64.0;
        double f2 = sh_mse[i] / tot;
        double f3 = (double)sh_pu[i] / (double)tu;
        sh_cand[i] = (float)((1.0 - f1 + f2 + f3) / 3.0);
    }
    __syncthreads();

    if (i == 0) {
        float p = 0.f;
        for (int j = 0; j < 64; ++j) p = fmaxf(p, sh_cand[j]);
        g_p = p;
        // scalar tail of x_out (N not multiple of 4), then p into out[N..)
        const float inv = 1.0f / (1.0f - p);
        for (long long k = (N >> 2) << 2; k < N; ++k)
            out[k] = (noise[k] >= p) ? x[k] * inv : 0.f;
        for (long long k = N; k < out_size; ++k) out[k] = p;
    }
}

// ----------------------------- dropout -------------------------------------
__global__ __launch_bounds__(256)
void dropout_kernel(const float* __restrict__ x, const float* __restrict__ noise,
                    float* __restrict__ out, long long n4) {
    const long long idx = (long long)blockIdx.x * blockDim.x + threadIdx.x;
    if (idx >= n4) return;
    const float p   = g_p;
    const float inv = 1.0f / (1.0f - p);
    float4 xv = reinterpret_cast<const float4*>(x)[idx];
    float4 nv = reinterpret_cast<const float4*>(noise)[idx];
    float4 o;
    o.x = (nv.x >= p) ? xv.x * inv : 0.f;
    o.y = (nv.y >= p) ? xv.y * inv : 0.f;
    o.z = (nv.z >= p) ? xv.z * inv : 0.f;
    o.w = (nv.w >= p) ? xv.w * inv : 0.f;
    reinterpret_cast<float4*>(out)[idx] = o;
}

// ----------------------------- launch --------------------------------------
extern "C" void kernel_launch(void* const* d_in, const int* in_sizes, int n_in,
                              void* d_out, int out_size) {
    const float* x     = (const float*)d_in[0];
    const float* noise = (const float*)d_in[1];
    float* out = (float*)d_out;

    const long long N = (long long)in_sizes[0];
    const int D = (int)(N / 64);
    const int ntiles = D >> 6;                 // D is a multiple of 64 here

    zero_kernel<<<16, 256>>>();

    int gblocks = ntiles < 784 ? ntiles : 784;
    gram_stats_kernel<<<gblocks, 256>>>(x, D, ntiles);

    finalize_kernel<<<1, 64>>>(x, noise, out, N, (long long)out_size, D);

    const long long n4 = N >> 2;
    const int dthreads = 256;
    const unsigned dblocks = (unsigned)((n4 + dthreads - 1) / dthreads);
    dropout_kernel<<<dblocks, dthreads>>>(x, noise, out, n4);
}

// round 3
// speedup vs baseline: 1.4332x; 1.4332x over previous
#include <cuda_runtime.h>
#include <cuda_bf16.h>
#include <cstdint>

// ---------------------------------------------------------------------------
// DifferentialDropout: x [64, D], noise [64, D]  (D = 512*28*28 = 401408)
//   1. gram_stats: one pass over x -> Gram G (64x64, bf16 tensor cores),
//      row sums S, per-row 1024-bin presence bitmasks. Double-buffered
//      smem pipeline: prefetch tile t+1 into registers while mma on tile t.
//   2. finalize: factors -> p  (parallel, inv-std multiplies, few fp64 divides)
//   3. dropout: out = noise >= p ? x/(1-p) : 0   (float4, streaming hints)
// ---------------------------------------------------------------------------

static __device__ float        g_S[64];
static __device__ float        g_G[64 * 64];
static __device__ unsigned int g_maskw[64 * 32];   // 1024 bins per row
static __device__ float        g_p;

// ---------------------------- zero scratch ---------------------------------
__global__ void zero_kernel() {
    int tid = blockIdx.x * blockDim.x + threadIdx.x;
    int stride = gridDim.x * blockDim.x;
    for (int i = tid; i < 64; i += stride)        g_S[i] = 0.f;
    for (int i = tid; i < 64 * 64; i += stride)   g_G[i] = 0.f;
    for (int i = tid; i < 64 * 32; i += stride)   g_maskw[i] = 0u;
}

// Swizzled bf16 tile, 64 rows x 128 bf16 = 64 u32 words per row.
// 16B chunk c (0..15) of row r lives at physical chunk c ^ (r&7)
// -> ldmatrix reads (8 rows, same logical chunk) are bank-conflict free.
__device__ __forceinline__ int swz(int r, int w) {
    return (r << 6) + ((((w >> 2) ^ (r & 7)) << 2) | (w & 3));
}

#define KTILE 128   // columns per tile

// ------------------- fused stats + bf16 Gram (reads x once) ----------------
__global__ __launch_bounds__(256, 2)
void gram_stats_kernel(const float* __restrict__ x, int D, int ntiles) {
    __shared__ uint32_t sh[2][64 * 64];   // two 16KB buffers

    const int tid  = threadIdx.x;
    const int lane = tid & 31;
    const int warp = tid >> 5;

    // loader mapping: 4 threads per row, 8 float4 per thread per tile
    const int lrow = tid >> 2;     // 0..63
    const int lc   = tid & 3;      // 0..3

    // compute mapping: warp = (mb, nh); covers 16 rows x 32 cols of G
    const int mb = warp & 3;
    const int nh = warp >> 2;
    const int i0 = mb << 4;

    // ldmatrix lane roles
    const int am  = lane & 7;
    const int atr = (lane >> 3) & 1;
    const int atc = lane >> 4;
    const int bm  = lane & 7;
    const int btl = (lane >> 3) & 1;

    float acc[4][4];
    #pragma unroll
    for (int t = 0; t < 4; ++t)
        #pragma unroll
        for (int r = 0; r < 4; ++r) acc[t][r] = 0.f;

    float rsum = 0.f;
    unsigned long long rmask = 0ull;

    const uint32_t sbase = (uint32_t)__cvta_generic_to_shared(&sh[0][0]);

    float4 v[8];
    int t = blockIdx.x;
    {
        const float* rp = x + (size_t)lrow * D + (size_t)t * KTILE;
        #pragma unroll
        for (int i = 0; i < 8; ++i)
            v[i] = *reinterpret_cast<const float4*>(rp + (((i << 2) + lc) << 2));
    }

    int buf = 0;
    while (t < ntiles) {
        // ---- convert + stats + store tile t into sh[buf] ----
        uint32_t* sb = &sh[buf][0];
        #pragma unroll
        for (int i = 0; i < 8; ++i) {
            const float4 vv = v[i];
            rsum += (vv.x + vv.y) + (vv.z + vv.w);
            float vals[4] = {vv.x, vv.y, vv.z, vv.w};
            #pragma unroll
            for (int e = 0; e < 4; ++e) {
                int b = __float2int_rn(vals[e]);            // == jnp.round
                if ((unsigned)(b + 32) < 64u) {
                    rmask |= 1ull << (b + 32);
                } else {                                    // never for N(0,1)
                    int wb = b + 512;
                    wb = wb < 0 ? 0 : (wb > 1023 ? 1023 : wb);
                    atomicOr(&g_maskw[(lrow << 5) + (wb >> 5)], 1u << (wb & 31));
                }
            }
            __nv_bfloat162 p0 = __floats2bfloat162_rn(vv.x, vv.y);
            __nv_bfloat162 p1 = __floats2bfloat162_rn(vv.z, vv.w);
            const int j4 = (i << 2) + lc;                   // float4 idx 0..31
            const int wi = swz(lrow, j4 << 1);
            sb[wi]     = *reinterpret_cast<uint32_t*>(&p0);
            sb[wi + 1] = *reinterpret_cast<uint32_t*>(&p1);
        }
        __syncthreads();

        // ---- prefetch tile t+gridDim into registers (overlaps mma) ----
        const int tn = t + gridDim.x;
        if (tn < ntiles) {
            const float* rp = x + (size_t)lrow * D + (size_t)tn * KTILE;
            #pragma unroll
            for (int i = 0; i < 8; ++i)
                v[i] = *reinterpret_cast<const float4*>(rp + (((i << 2) + lc) << 2));
        }

        // ---- Gram update on sh[buf]: 8 k-steps of 16 ----
        const uint32_t bufb = sbase + (uint32_t)(buf * 16384);
        #pragma unroll
        for (int ks = 0; ks < 8; ++ks) {
            const int cb = ks << 1;
            uint32_t a0, a1, a2, a3;
            {
                int r = i0 + (atr << 3) + am;   // (r & 7) == am
                uint32_t addr = bufb + (uint32_t)((r << 8) + (((cb + atc) ^ am) << 4));
                asm volatile("ldmatrix.sync.aligned.m8n8.x4.shared.b16 {%0,%1,%2,%3}, [%4];"
                             : "=r"(a0), "=r"(a1), "=r"(a2), "=r"(a3) : "r"(addr));
            }
            #pragma unroll
            for (int nt = 0; nt < 4; ++nt) {
                const int j0 = (nh << 5) + (nt << 3);
                uint32_t b0, b1;
                {
                    int r = j0 + bm;            // (r & 7) == bm
                    uint32_t addr = bufb + (uint32_t)((r << 8) + (((cb + btl) ^ bm) << 4));
                    asm volatile("ldmatrix.sync.aligned.m8n8.x2.shared.b16 {%0,%1}, [%2];"
                                 : "=r"(b0), "=r"(b1) : "r"(addr));
                }
                asm volatile("mma.sync.aligned.m16n8k16.row.col.f32.bf16.bf16.f32 "
                             "{%0,%1,%2,%3}, {%4,%5,%6,%7}, {%8,%9}, {%0,%1,%2,%3};"
                             : "+f"(acc[nt][0]), "+f"(acc[nt][1]),
                               "+f"(acc[nt][2]), "+f"(acc[nt][3])
                             : "r"(a0), "r"(a1), "r"(a2), "r"(a3), "r"(b0), "r"(b1));
            }
        }
        buf ^= 1;
        t = tn;
    }

    // ---- per-row stats reduce (4 adjacent lanes per row) ----
    rsum += __shfl_xor_sync(0xffffffffu, rsum, 1);
    rsum += __shfl_xor_sync(0xffffffffu, rsum, 2);
    rmask |= __shfl_xor_sync(0xffffffffu, rmask, 1);
    rmask |= __shfl_xor_sync(0xffffffffu, rmask, 2);
    if (lc == 0) {
        atomicAdd(&g_S[lrow], rsum);
        // local bit (b+32) maps to wide bins 480..543 = words 15,16
        atomicOr(&g_maskw[(lrow << 5) + 15], (uint32_t)(rmask & 0xffffffffull));
        atomicOr(&g_maskw[(lrow << 5) + 16], (uint32_t)(rmask >> 32));
    }

    // ---- Gram partials -> global ----
    const int oi = i0 + (lane >> 2);
    #pragma unroll
    for (int nt = 0; nt < 4; ++nt) {
        const int oj = (nh << 5) + (nt << 3) + ((lane & 3) << 1);
        atomicAdd(&g_G[oi * 64 + oj],           acc[nt][0]);
        atomicAdd(&g_G[oi * 64 + oj + 1],       acc[nt][1]);
        atomicAdd(&g_G[(oi + 8) * 64 + oj],     acc[nt][2]);
        atomicAdd(&g_G[(oi + 8) * 64 + oj + 1], acc[nt][3]);
    }
}

// ----------------------------- finalize ------------------------------------
__global__ __launch_bounds__(256)
void finalize_kernel(const float* __restrict__ x,
                     const float* __restrict__ noise,
                     float* __restrict__ out,
                     long long N, long long out_size, int D) {
    __shared__ double       sh_S[64], sh_inv[64], sh_R[64], sh_mse[64];
    __shared__ int          sh_pu[64];
    __shared__ unsigned int sh_orw[32];
    __shared__ float        sh_cand[64];

    const int tid  = threadIdx.x;
    const int row  = tid >> 2;     // 0..63
    const int q    = tid & 3;      // 0..3  (16-wide j stripes)
    const double Dd    = (double)D;
    const double invD  = 1.0 / Dd;
    const double invDm1 = 1.0 / (Dd - 1.0);

    if (tid < 32) sh_orw[tid] = 0u;
    __syncthreads();

    // R_i (row sums of G), per-row unique popcount, global OR-mask
    {
        double R = 0.0;
        #pragma unroll
        for (int j = 0; j < 16; ++j) R += (double)g_G[row * 64 + (q << 4) + j];
        R += __shfl_xor_sync(0xffffffffu, R, 1);
        R += __shfl_xor_sync(0xffffffffu, R, 2);

        int pu = 0;
        #pragma unroll
        for (int w = 0; w < 8; ++w) {
            unsigned m = g_maskw[row * 32 + (q << 3) + w];
            pu += __popc(m);
            atomicOr(&sh_orw[(q << 3) + w], m);
        }
        pu += __shfl_xor_sync(0xffffffffu, pu, 1);
        pu += __shfl_xor_sync(0xffffffffu, pu, 2);

        if (q == 0) {
            sh_R[row]  = R;
            sh_pu[row] = pu;
            sh_S[row]  = (double)g_S[row];
        }
    }
    __syncthreads();

    if (tid < 64) {
        double Si = sh_S[tid];
        double covii = ((double)g_G[tid * 64 + tid] - Si * Si * invD) * invDm1;
        sh_inv[tid] = 1.0 / sqrt(covii);
        double T = 0.0;
        for (int j = 0; j < 64; ++j) T += sh_R[j];
        sh_mse[tid] = ((double)g_G[tid * 64 + tid]
                       - 2.0 * sh_R[tid] / 64.0 + T / 4096.0) * invD;
    }
    __syncthreads();

    // f1 per row: 4 threads/row, inv-std multiplies (no per-pair divides)
    {
        const double Si  = sh_S[row];
        const double ivi = sh_inv[row];
        double f1 = 0.0;
        #pragma unroll
        for (int j = 0; j < 16; ++j) {
            const int jj = (q << 4) + j;
            double cov = ((double)g_G[row * 64 + jj] - Si * sh_S[jj] * invD) * invDm1;
            double c = cov * ivi * sh_inv[jj];
            c = fmin(fmax(c, -1.0), 1.0);
            f1 += fabs(c);
        }
        f1 += __shfl_xor_sync(0xffffffffu, f1, 1);
        f1 += __shfl_xor_sync(0xffffffffu, f1, 2);

        if (q == 0) {
            double tot = 0.0;
            for (int j = 0; j < 64; ++j) tot += sh_mse[j];
            int tu = 0;
            for (int w = 0; w < 32; ++w) tu += __popc(sh_orw[w]);
            double f2 = sh_mse[row] / tot;
            double f3 = (double)sh_pu[row] / (double)tu;
            sh_cand[row] = (float)((1.0 - f1 / 64.0 + f2 + f3) / 3.0);
        }
    }
    __syncthreads();

    if (tid == 0) {
        float p = 0.f;
        for (int j = 0; j < 64; ++j) p = fmaxf(p, sh_cand[j]);
        g_p = p;
        const float inv = 1.0f / (1.0f - p);
        for (long long k = (N >> 2) << 2; k < N; ++k)
            out[k] = (noise[k] >= p) ? x[k] * inv : 0.f;
        for (long long k = N; k < out_size; ++k) out[k] = p;
    }
}

// ----------------------------- dropout -------------------------------------
__global__ __launch_bounds__(256)
void dropout_kernel(const float* __restrict__ x, const float* __restrict__ noise,
                    float* __restrict__ out, long long n4) {
    const long long idx = (long long)blockIdx.x * blockDim.x + threadIdx.x;
    if (idx >= n4) return;
    const float p   = g_p;
    const float inv = 1.0f / (1.0f - p);
    float4 xv = reinterpret_cast<const float4*>(x)[idx];
    float4 nv = __ldcs(reinterpret_cast<const float4*>(noise) + idx);
    float4 o;
    o.x = (nv.x >= p) ? xv.x * inv : 0.f;
    o.y = (nv.y >= p) ? xv.y * inv : 0.f;
    o.z = (nv.z >= p) ? xv.z * inv : 0.f;
    o.w = (nv.w >= p) ? xv.w * inv : 0.f;
    __stcs(reinterpret_cast<float4*>(out) + idx, o);
}

// ----------------------------- launch --------------------------------------
extern "C" void kernel_launch(void* const* d_in, const int* in_sizes, int n_in,
                              void* d_out, int out_size) {
    const float* x     = (const float*)d_in[0];
    const float* noise = (const float*)d_in[1];
    float* out = (float*)d_out;

    const long long N = (long long)in_sizes[0];
    const int D = (int)(N / 64);
    const int ntiles = D / KTILE;              // D = 401408 -> 3136 tiles

    zero_kernel<<<16, 256>>>();

    int gblocks = ntiles < 296 ? ntiles : 296; // 2 even waves at 2 CTAs/SM
    gram_stats_kernel<<<gblocks, 256>>>(x, D, ntiles);

    finalize_kernel<<<1, 256>>>(x, noise, out, N, (long long)out_size, D);

    const long long n4 = N >> 2;
    const int dthreads = 256;
    const unsigned dblocks = (unsigned)((n4 + dthreads - 1) / dthreads);
    dropout_kernel<<<dblocks, dthreads>>>(x, noise, out, n4);
}

// round 4
// speedup vs baseline: 1.4343x; 1.0007x over previous
#include <cuda_runtime.h>
#include <cuda_bf16.h>
#include <cstdint>

// ---------------------------------------------------------------------------
// DifferentialDropout: x [64, D], noise [64, D]  (D = 512*28*28 = 401408)
//   1. gram_stats: one pass over x -> Gram G (64x64, bf16 tensor cores),
//      row sums S, per-row 1024-bin presence bitmasks. Double-buffered smem,
//      prefetch issued before the barrier, k-split 32x32 warp tiles (all
//      fragments via ldmatrix.x4), k-halves merged in smem before REDG.
//   2. finalize: factors -> p  (parallel, inv-std multiplies)
//   3. dropout: out = noise >= p ? x/(1-p) : 0; block 0 re-zeroes scratch
//      for the next graph replay (initial state is .bss-zero).
// ---------------------------------------------------------------------------

static __device__ float        g_S[64];
static __device__ float        g_G[64 * 64];
static __device__ unsigned int g_maskw[64 * 32];   // 1024 bins per row
static __device__ float        g_p;

// Swizzled bf16 tile, 64 rows x 128 bf16 = 64 u32 words per row.
// 16B chunk c (0..15) of row r lives at physical chunk c ^ (r&7).
__device__ __forceinline__ int swz(int r, int w) {
    return (r << 6) + ((((w >> 2) ^ (r & 7)) << 2) | (w & 3));
}

#define KTILE 128   // columns per tile

// ------------------- fused stats + bf16 Gram (reads x once) ----------------
__global__ __launch_bounds__(256, 2)
void gram_stats_kernel(const float* __restrict__ x, int D, int ntiles) {
    __shared__ uint32_t sh[2][64 * 64];   // two 16KB buffers

    const int tid  = threadIdx.x;
    const int lane = tid & 31;
    const int warp = tid >> 5;

    // loader mapping: 4 threads per row, 8 float4 per thread per tile
    const int lrow = tid >> 2;     // 0..63
    const int lc   = tid & 3;      // 0..3

    // compute mapping: warp = (ib, jb, kh) -> 32x32 tile of G over half of k
    const int kh = warp & 1;         // k-half: chunks kh*8 .. kh*8+7
    const int jb = (warp >> 1) & 1;  // col block
    const int ib = warp >> 2;        // row block
    const int i0 = ib << 5;
    const int j0 = jb << 5;

    const int lrf = lane & 15;       // ldmatrix fragment row
    const int lch = lane >> 4;       // ldmatrix fragment chunk offset

    float acc[2][4][4];
    #pragma unroll
    for (int h = 0; h < 2; ++h)
        #pragma unroll
        for (int t = 0; t < 4; ++t)
            #pragma unroll
            for (int r = 0; r < 4; ++r) acc[h][t][r] = 0.f;

    float rsum = 0.f;
    unsigned long long rmask = 0ull;

    const uint32_t sbase = (uint32_t)__cvta_generic_to_shared(&sh[0][0]);

    float4 v[8];
    int t = blockIdx.x;
    {
        const float* rp = x + (size_t)lrow * D + (size_t)t * KTILE;
        #pragma unroll
        for (int i = 0; i < 8; ++i)
            v[i] = *reinterpret_cast<const float4*>(rp + (((i << 2) + lc) << 2));
    }

    int buf = 0;
    while (t < ntiles) {
        // ---- convert + stats + store tile t into sh[buf] ----
        uint32_t* sb = &sh[buf][0];
        #pragma unroll
        for (int i = 0; i < 8; ++i) {
            const float4 vv = v[i];
            rsum += (vv.x + vv.y) + (vv.z + vv.w);
            float vals[4] = {vv.x, vv.y, vv.z, vv.w};
            #pragma unroll
            for (int e = 0; e < 4; ++e) {
                int b = __float2int_rn(vals[e]);            // == jnp.round
                if ((unsigned)(b + 32) < 64u) {
                    rmask |= 1ull << (b + 32);
                } else {                                    // never for N(0,1)
                    int wb = b + 512;
                    wb = wb < 0 ? 0 : (wb > 1023 ? 1023 : wb);
                    atomicOr(&g_maskw[(lrow << 5) + (wb >> 5)], 1u << (wb & 31));
                }
            }
            __nv_bfloat162 p0 = __floats2bfloat162_rn(vv.x, vv.y);
            __nv_bfloat162 p1 = __floats2bfloat162_rn(vv.z, vv.w);
            const int wi = swz(lrow, ((i << 2) + lc) << 1);  // even word idx
            uint2 pk;
            pk.x = *reinterpret_cast<uint32_t*>(&p0);
            pk.y = *reinterpret_cast<uint32_t*>(&p1);
            *reinterpret_cast<uint2*>(&sb[wi]) = pk;
        }

        // ---- prefetch tile t+grid BEFORE barrier (v[] dead, overlaps sync+mma)
        const int tn = t + gridDim.x;
        if (tn < ntiles) {
            const float* rp = x + (size_t)lrow * D + (size_t)tn * KTILE;
            #pragma unroll
            for (int i = 0; i < 8; ++i)
                v[i] = *reinterpret_cast<const float4*>(rp + (((i << 2) + lc) << 2));
        }
        __syncthreads();

        // ---- Gram update on sh[buf]: this warp's k-half, 4 k-steps of 16 ----
        const uint32_t bufb = sbase + (uint32_t)(buf * 16384);
        #pragma unroll
        for (int ks = 0; ks < 4; ++ks) {
            const int cb = (kh << 3) + (ks << 1);
            uint32_t a[2][4], bfr[2][4];
            #pragma unroll
            for (int h = 0; h < 2; ++h) {
                int r = i0 + (h << 4) + lrf;
                uint32_t addr = bufb + (uint32_t)((r << 8) + (((cb + lch) ^ (r & 7)) << 4));
                asm volatile("ldmatrix.sync.aligned.m8n8.x4.shared.b16 {%0,%1,%2,%3}, [%4];"
                             : "=r"(a[h][0]), "=r"(a[h][1]), "=r"(a[h][2]), "=r"(a[h][3])
                             : "r"(addr));
            }
            #pragma unroll
            for (int g = 0; g < 2; ++g) {
                int r = j0 + (g << 4) + lrf;
                uint32_t addr = bufb + (uint32_t)((r << 8) + (((cb + lch) ^ (r & 7)) << 4));
                asm volatile("ldmatrix.sync.aligned.m8n8.x4.shared.b16 {%0,%1,%2,%3}, [%4];"
                             : "=r"(bfr[g][0]), "=r"(bfr[g][1]), "=r"(bfr[g][2]), "=r"(bfr[g][3])
                             : "r"(addr));
            }
            #pragma unroll
            for (int h = 0; h < 2; ++h)
                #pragma unroll
                for (int g = 0; g < 2; ++g)
                    #pragma unroll
                    for (int f = 0; f < 2; ++f) {
                        const int nt = (g << 1) + f;
                        asm volatile("mma.sync.aligned.m16n8k16.row.col.f32.bf16.bf16.f32 "
                                     "{%0,%1,%2,%3}, {%4,%5,%6,%7}, {%8,%9}, {%0,%1,%2,%3};"
                                     : "+f"(acc[h][nt][0]), "+f"(acc[h][nt][1]),
                                       "+f"(acc[h][nt][2]), "+f"(acc[h][nt][3])
                                     : "r"(a[h][0]), "r"(a[h][1]), "r"(a[h][2]), "r"(a[h][3]),
                                       "r"(bfr[g][f]), "r"(bfr[g][f + 2]));
                    }
        }
        buf ^= 1;
        t = tn;
    }

    // ---- per-row stats reduce (4 adjacent lanes per row) ----
    rsum += __shfl_xor_sync(0xffffffffu, rsum, 1);
    rsum += __shfl_xor_sync(0xffffffffu, rsum, 2);
    rmask |= __shfl_xor_sync(0xffffffffu, rmask, 1);
    rmask |= __shfl_xor_sync(0xffffffffu, rmask, 2);
    if (lc == 0) {
        atomicAdd(&g_S[lrow], rsum);
        // local bit (b+32) maps to wide bins 480..543 = words 15,16
        atomicOr(&g_maskw[(lrow << 5) + 15], (uint32_t)(rmask & 0xffffffffull));
        atomicOr(&g_maskw[(lrow << 5) + 16], (uint32_t)(rmask >> 32));
    }

    // ---- merge k-halves in smem, then one REDG set (kh==0 warps only) ----
    __syncthreads();
    float* shf = reinterpret_cast<float*>(&sh[0][0]);   // 64x64 f32 = 16KB
    const int orow = lane >> 2;
    const int ocol = (lane & 3) << 1;
    if (kh == 1) {
        #pragma unroll
        for (int h = 0; h < 2; ++h)
            #pragma unroll
            for (int g = 0; g < 2; ++g)
                #pragma unroll
                for (int f = 0; f < 2; ++f) {
                    const int nt = (g << 1) + f;
                    const int oi = i0 + (h << 4) + orow;
                    const int oj = j0 + (g << 4) + (f << 3) + ocol;
                    shf[oi * 64 + oj]           = acc[h][nt][0];
                    shf[oi * 64 + oj + 1]       = acc[h][nt][1];
                    shf[(oi + 8) * 64 + oj]     = acc[h][nt][2];
                    shf[(oi + 8) * 64 + oj + 1] = acc[h][nt][3];
                }
    }
    __syncthreads();
    if (kh == 0) {
        #pragma unroll
        for (int h = 0; h < 2; ++h)
            #pragma unroll
            for (int g = 0; g < 2; ++g)
                #pragma unroll
                for (int f = 0; f < 2; ++f) {
                    const int nt = (g << 1) + f;
                    const int oi = i0 + (h << 4) + orow;
                    const int oj = j0 + (g << 4) + (f << 3) + ocol;
                    atomicAdd(&g_G[oi * 64 + oj],
                              acc[h][nt][0] + shf[oi * 64 + oj]);
                    atomicAdd(&g_G[oi * 64 + oj + 1],
                              acc[h][nt][1] + shf[oi * 64 + oj + 1]);
                    atomicAdd(&g_G[(oi + 8) * 64 + oj],
                              acc[h][nt][2] + shf[(oi + 8) * 64 + oj]);
                    atomicAdd(&g_G[(oi + 8) * 64 + oj + 1],
                              acc[h][nt][3] + shf[(oi + 8) * 64 + oj + 1]);
                }
    }
}

// ----------------------------- finalize ------------------------------------
__global__ __launch_bounds__(256)
void finalize_kernel(const float* __restrict__ x,
                     const float* __restrict__ noise,
                     float* __restrict__ out,
                     long long N, long long out_size, int D) {
    __shared__ double       sh_S[64], sh_inv[64], sh_R[64], sh_mse[64];
    __shared__ int          sh_pu[64];
    __shared__ unsigned int sh_orw[32];
    __shared__ float        sh_cand[64];

    const int tid  = threadIdx.x;
    const int row  = tid >> 2;     // 0..63
    const int q    = tid & 3;      // 0..3  (16-wide j stripes)
    const double Dd    = (double)D;
    const double invD  = 1.0 / Dd;
    const double invDm1 = 1.0 / (Dd - 1.0);

    if (tid < 32) sh_orw[tid] = 0u;
    __syncthreads();

    {
        double R = 0.0;
        #pragma unroll
        for (int j = 0; j < 16; ++j) R += (double)g_G[row * 64 + (q << 4) + j];
        R += __shfl_xor_sync(0xffffffffu, R, 1);
        R += __shfl_xor_sync(0xffffffffu, R, 2);

        int pu = 0;
        #pragma unroll
        for (int w = 0; w < 8; ++w) {
            unsigned m = g_maskw[row * 32 + (q << 3) + w];
            pu += __popc(m);
            atomicOr(&sh_orw[(q << 3) + w], m);
        }
        pu += __shfl_xor_sync(0xffffffffu, pu, 1);
        pu += __shfl_xor_sync(0xffffffffu, pu, 2);

        if (q == 0) {
            sh_R[row]  = R;
            sh_pu[row] = pu;
            sh_S[row]  = (double)g_S[row];
        }
    }
    __syncthreads();

    if (tid < 64) {
        double Si = sh_S[tid];
        double covii = ((double)g_G[tid * 64 + tid] - Si * Si * invD) * invDm1;
        sh_inv[tid] = 1.0 / sqrt(covii);
        double T = 0.0;
        for (int j = 0; j < 64; ++j) T += sh_R[j];
        sh_mse[tid] = ((double)g_G[tid * 64 + tid]
                       - 2.0 * sh_R[tid] / 64.0 + T / 4096.0) * invD;
    }
    __syncthreads();

    {
        const double Si  = sh_S[row];
        const double ivi = sh_inv[row];
        double f1 = 0.0;
        #pragma unroll
        for (int j = 0; j < 16; ++j) {
            const int jj = (q << 4) + j;
            double cov = ((double)g_G[row * 64 + jj] - Si * sh_S[jj] * invD) * invDm1;
            double c = cov * ivi * sh_inv[jj];
            c = fmin(fmax(c, -1.0), 1.0);
            f1 += fabs(c);
        }
        f1 += __shfl_xor_sync(0xffffffffu, f1, 1);
        f1 += __shfl_xor_sync(0xffffffffu, f1, 2);

        if (q == 0) {
            double tot = 0.0;
            for (int j = 0; j < 64; ++j) tot += sh_mse[j];
            int tu = 0;
            for (int w = 0; w < 32; ++w) tu += __popc(sh_orw[w]);
            double f2 = sh_mse[row] / tot;
            double f3 = (double)sh_pu[row] / (double)tu;
            sh_cand[row] = (float)((1.0 - f1 / 64.0 + f2 + f3) / 3.0);
        }
    }
    __syncthreads();

    if (tid == 0) {
        float p = 0.f;
        for (int j = 0; j < 64; ++j) p = fmaxf(p, sh_cand[j]);
        g_p = p;
        const float inv = 1.0f / (1.0f - p);
        for (long long k = (N >> 2) << 2; k < N; ++k)
            out[k] = (noise[k] >= p) ? x[k] * inv : 0.f;
        for (long long k = N; k < out_size; ++k) out[k] = p;
    }
}

// ----------------------------- dropout -------------------------------------
__global__ __launch_bounds__(256)
void dropout_kernel(const float* __restrict__ x, const float* __restrict__ noise,
                    float* __restrict__ out, long long n4) {
    const long long idx = (long long)blockIdx.x * blockDim.x + threadIdx.x;
    const float p   = g_p;
    const float inv = 1.0f / (1.0f - p);
    if (idx < n4) {
        float4 xv = reinterpret_cast<const float4*>(x)[idx];
        float4 nv = __ldcs(reinterpret_cast<const float4*>(noise) + idx);
        float4 o;
        o.x = (nv.x >= p) ? xv.x * inv : 0.f;
        o.y = (nv.y >= p) ? xv.y * inv : 0.f;
        o.z = (nv.z >= p) ? xv.z * inv : 0.f;
        o.w = (nv.w >= p) ? xv.w * inv : 0.f;
        __stcs(reinterpret_cast<float4*>(out) + idx, o);
    }
    // block 0 resets scratch for the next graph replay (initial state = .bss 0;
    // finalize of THIS replay has already consumed these; g_p is rewritten by
    // finalize before any dropout reads it, so it needs no reset).
    if (blockIdx.x == 0) {
        const int t = threadIdx.x;
        for (int i = t; i < 64; i += 256)      g_S[i] = 0.f;
        for (int i = t; i < 64 * 64; i += 256) g_G[i] = 0.f;
        for (int i = t; i < 64 * 32; i += 256) g_maskw[i] = 0u;
    }
}

// ----------------------------- launch --------------------------------------
extern "C" void kernel_launch(void* const* d_in, const int* in_sizes, int n_in,
                              void* d_out, int out_size) {
    const float* x     = (const float*)d_in[0];
    const float* noise = (const float*)d_in[1];
    float* out = (float*)d_out;

    const long long N = (long long)in_sizes[0];
    const int D = (int)(N / 64);
    const int ntiles = D / KTILE;              // D = 401408 -> 3136 tiles

    int gblocks = ntiles < 296 ? ntiles : 296; // one full wave at 2 CTAs/SM
    gram_stats_kernel<<<gblocks, 256>>>(x, D, ntiles);

    finalize_kernel<<<1, 256>>>(x, noise, out, N, (long long)out_size, D);

    const long long n4 = N >> 2;
    const int dthreads = 256;
    const unsigned dblocks = (unsigned)((n4 + dthreads - 1) / dthreads);
    dropout_kernel<<<dblocks, dthreads>>>(x, noise, out, n4);
}